// round 11
// baseline (speedup 1.0000x reference)
#include <cuda_runtime.h>
#include <cstdint>

#define HDIM 64
#define KD1 128   // 2H
#define C1 256    // 4H
#define C2 64     // H
#define NMAX 65536
#define EMAXN 1048576

__device__ float g_P[(size_t)NMAX * C1];      // emb @ W1_top  (norm-folded in place)
__device__ float g_Q[(size_t)NMAX * C1];      // emb @ W1_bot  (norm-folded in place)
__device__ float g_h2[(size_t)EMAXN * C2];    // layer-2 pre-norm [e][c]
__device__ int   g_col[EMAXN], g_row[EMAXN];  // canonical int32 indices
__device__ float g_sum1[C1], g_ssq1[C1];
__device__ float g_sum2[C2], g_ssq2[C2];

// ---------- f32x2 packed-FMA helpers (FFMA2; only reachable via PTX) ----------
__device__ __forceinline__ unsigned long long pack2(float lo, float hi) {
    unsigned long long r;
    asm("mov.b64 %0, {%1, %2};" : "=l"(r) : "f"(lo), "f"(hi));
    return r;
}
__device__ __forceinline__ void fma2(unsigned long long& d, unsigned long long a,
                                     unsigned long long b) {
    asm("fma.rn.f32x2 %0, %1, %2, %0;" : "+l"(d) : "l"(a), "l"(b));
}
__device__ __forceinline__ float2 unpack2(unsigned long long v) {
    float lo, hi;
    asm("mov.b64 {%0, %1}, %2;" : "=f"(lo), "=f"(hi) : "l"(v));
    return make_float2(lo, hi);
}

// Named-barrier producer/consumer primitives (ids 1..4; 0 reserved for __syncthreads)
#define BAR_SYNC(id)   asm volatile("bar.sync %0, 512;"   :: "r"(id) : "memory")
#define BAR_ARRIVE(id) asm volatile("bar.arrive %0, 512;" :: "r"(id) : "memory")

// Inline dtype sniff: safe under both interpretations (reads first min(16,E) 8B).
__device__ __forceinline__ int sniff64(const void* eidx, int E, int N) {
    const long long* p64 = (const long long*)eidx;
    int n = E < 16 ? E : 16;
    int ok = 1;
    for (int i = 0; i < n; i++) {
        long long v = p64[i];
        if (v < 0 || v >= (long long)N) ok = 0;
    }
    return ok;
}

// ---------- K1a: convert col indices (+ block0 zeroes stats accumulators) ----------
__global__ void __launch_bounds__(256) k_cvt_col(const void* eidx, int E, int N) {
    __shared__ int s64;
    if (threadIdx.x == 0) s64 = sniff64(eidx, E, N);
    if (blockIdx.x == 0) {
        int t = threadIdx.x;
        if (t < C1) { g_sum1[t] = 0.f; g_ssq1[t] = 0.f; }
        if (t < C2) { g_sum2[t] = 0.f; g_ssq2[t] = 0.f; }
    }
    __syncthreads();
    const int stride = gridDim.x * 256;
    if (s64) {
        const long long* p = (const long long*)eidx;
        for (int e = blockIdx.x * 256 + threadIdx.x; e < E; e += stride)
            g_col[e] = (int)p[e];
    } else {
        const int* p = (const int*)eidx;
        for (int e = blockIdx.x * 256 + threadIdx.x; e < E; e += stride)
            g_col[e] = p[e];
    }
}

// ---------- K1b: convert row indices ----------
__global__ void __launch_bounds__(256) k_cvt_row(const void* eidx, int E, int N) {
    __shared__ int s64;
    if (threadIdx.x == 0) s64 = sniff64(eidx, E, N);
    __syncthreads();
    const int stride = gridDim.x * 256;
    if (s64) {
        const long long* p = (const long long*)eidx;
        for (int e = blockIdx.x * 256 + threadIdx.x; e < E; e += stride)
            g_row[e] = (int)p[E + e];
    } else {
        const int* p = (const int*)eidx;
        for (int e = blockIdx.x * 256 + threadIdx.x; e < E; e += stride)
            g_row[e] = p[E + e];
    }
}

// ---------- K2: node-level pre-GEMM  P = emb@W1_top, Q = emb@W1_bot ----------
#define SMEMP_BYTES (64 * 512 * 4 + 32 * 64 * 8)   // 147456

__global__ void __launch_bounds__(256, 1) k_pre(
    const float* __restrict__ emb, const float* __restrict__ W1, int N)
{
    extern __shared__ float smem[];
    float* ws = smem;                                                  // [64][512]
    unsigned long long* xsd = (unsigned long long*)(smem + 64 * 512);  // [32][64] dup

    const int tid = threadIdx.x;
    {
        const float4* w4 = (const float4*)W1;
        float4* ws4 = (float4*)ws;
        #pragma unroll 8
        for (int i = tid; i < 64 * 128; i += 256) {
            int k = i >> 7, c4 = i & 127;
            ws4[i] = (c4 < 64) ? w4[k * 64 + c4] : w4[4096 + k * 64 + (c4 - 64)];
        }
    }

    const int eg = tid >> 5;
    const int cg = tid & 31;
    const int c0 = cg * 4;
    const int nchunk = (N + 31) >> 5;

    for (int ch = blockIdx.x; ch < nchunk; ch += gridDim.x) {
        const int base = ch << 5;
        __syncthreads();
        #pragma unroll 2
        for (int i = tid; i < 512; i += 256) {
            int n = i >> 4, k4 = i & 15;
            float4 v = make_float4(0.f, 0.f, 0.f, 0.f);
            if (base + n < N)
                v = ((const float4*)emb)[(size_t)(base + n) * 16 + k4];
            ulonglong2* d = (ulonglong2*)(xsd + n * 64 + k4 * 4);
            d[0] = make_ulonglong2(pack2(v.x, v.x), pack2(v.y, v.y));
            d[1] = make_ulonglong2(pack2(v.z, v.z), pack2(v.w, v.w));
        }
        __syncthreads();

        unsigned long long acc[4][4][2];
        #pragma unroll
        for (int j = 0; j < 4; j++)
            #pragma unroll
            for (int h = 0; h < 4; h++) { acc[j][h][0] = 0ull; acc[j][h][1] = 0ull; }

        const unsigned long long* xrow = xsd + (eg * 4) * 64;
        #pragma unroll 2
        for (int k = 0; k < 64; k++) {
            ulonglong2 w0  = *(const ulonglong2*)(ws + k * 512 +   0 + c0);
            ulonglong2 w1v = *(const ulonglong2*)(ws + k * 512 + 128 + c0);
            ulonglong2 w2v = *(const ulonglong2*)(ws + k * 512 + 256 + c0);
            ulonglong2 w3v = *(const ulonglong2*)(ws + k * 512 + 384 + c0);
            #pragma unroll
            for (int j = 0; j < 4; j++) {
                unsigned long long xx = xrow[j * 64 + k];
                fma2(acc[j][0][0], w0.x, xx);  fma2(acc[j][0][1], w0.y, xx);
                fma2(acc[j][1][0], w1v.x, xx); fma2(acc[j][1][1], w1v.y, xx);
                fma2(acc[j][2][0], w2v.x, xx); fma2(acc[j][2][1], w2v.y, xx);
                fma2(acc[j][3][0], w3v.x, xx); fma2(acc[j][3][1], w3v.y, xx);
            }
        }

        #pragma unroll
        for (int j = 0; j < 4; j++) {
            int n = base + eg * 4 + j;
            if (n < N) {
                #pragma unroll
                for (int h = 0; h < 4; h++) {
                    float2 a  = unpack2(acc[j][h][0]);
                    float2 bq = unpack2(acc[j][h][1]);
                    float4 v = make_float4(a.x, a.y, bq.x, bq.y);
                    if (h < 2)
                        *(float4*)&g_P[(size_t)n * C1 + h * 128 + c0] = v;
                    else
                        *(float4*)&g_Q[(size_t)n * C1 + (h - 2) * 128 + c0] = v;
                }
            }
        }
    }
}

// ---------- K3: layer-1 stats over h1 = P[col]+Q[row]+b1 (2-edge ILP batches) ----------
__global__ void __launch_bounds__(256) k_stats1(const float* __restrict__ b1, int E)
{
    __shared__ float bsum[C1], bssq[C1];
    const int tid = threadIdx.x;
    const int lane = tid & 31, wid = tid >> 5;
    const int c0 = lane * 8;
    if (tid < C1) { bsum[tid] = 0.f; bssq[tid] = 0.f; }
    __syncthreads();

    float bb[8];
    #pragma unroll
    for (int i = 0; i < 8; i++) bb[i] = b1[c0 + i];
    float lsum[8], lssq[8];
    #pragma unroll
    for (int i = 0; i < 8; i++) { lsum[i] = 0.f; lssq[i] = 0.f; }

    const int stride = gridDim.x * 8;
    const int stride2 = stride * 2;
    for (int e = blockIdx.x * 8 + wid; e < E; e += stride2) {
        const int e2 = e + stride;
        const bool has2 = (e2 < E);
        int col1 = g_col[e], row1 = g_row[e];
        int col2 = has2 ? g_col[e2] : col1;
        int row2 = has2 ? g_row[e2] : row1;
        const float4* pp1 = (const float4*)(g_P + (size_t)col1 * C1 + c0);
        const float4* qq1 = (const float4*)(g_Q + (size_t)row1 * C1 + c0);
        const float4* pp2 = (const float4*)(g_P + (size_t)col2 * C1 + c0);
        const float4* qq2 = (const float4*)(g_Q + (size_t)row2 * C1 + c0);
        float4 a0 = pp1[0], a1 = pp1[1], b0 = qq1[0], b1v = qq1[1];
        float4 c0v = pp2[0], c1v = pp2[1], d0 = qq2[0], d1 = qq2[1];
        float h;
        h = a0.x + b0.x + bb[0]; lsum[0] += h; lssq[0] += h * h;
        h = a0.y + b0.y + bb[1]; lsum[1] += h; lssq[1] += h * h;
        h = a0.z + b0.z + bb[2]; lsum[2] += h; lssq[2] += h * h;
        h = a0.w + b0.w + bb[3]; lsum[3] += h; lssq[3] += h * h;
        h = a1.x + b1v.x + bb[4]; lsum[4] += h; lssq[4] += h * h;
        h = a1.y + b1v.y + bb[5]; lsum[5] += h; lssq[5] += h * h;
        h = a1.z + b1v.z + bb[6]; lsum[6] += h; lssq[6] += h * h;
        h = a1.w + b1v.w + bb[7]; lsum[7] += h; lssq[7] += h * h;
        if (has2) {
            h = c0v.x + d0.x + bb[0]; lsum[0] += h; lssq[0] += h * h;
            h = c0v.y + d0.y + bb[1]; lsum[1] += h; lssq[1] += h * h;
            h = c0v.z + d0.z + bb[2]; lsum[2] += h; lssq[2] += h * h;
            h = c0v.w + d0.w + bb[3]; lsum[3] += h; lssq[3] += h * h;
            h = c1v.x + d1.x + bb[4]; lsum[4] += h; lssq[4] += h * h;
            h = c1v.y + d1.y + bb[5]; lsum[5] += h; lssq[5] += h * h;
            h = c1v.z + d1.z + bb[6]; lsum[6] += h; lssq[6] += h * h;
            h = c1v.w + d1.w + bb[7]; lsum[7] += h; lssq[7] += h * h;
        }
    }
    #pragma unroll
    for (int i = 0; i < 8; i++) {
        atomicAdd(&bsum[c0 + i], lsum[i]);
        atomicAdd(&bssq[c0 + i], lssq[i]);
    }
    __syncthreads();
    if (tid < C1) {
        atomicAdd(&g_sum1[tid], bsum[tid]);
        atomicAdd(&g_ssq1[tid], bssq[tid]);
    }
}

// ---------- K4: fold norm affine into P/Q in place (finalize stats1 per-block) ----------
// P' = P * r1 ; Q' = (Q + b1 - m1) * r1
__global__ void __launch_bounds__(256) k_fold(const float* __restrict__ b1, int N, float invE)
{
    __shared__ float sr[C1], sq[C1];
    const int tid = threadIdx.x;
    if (tid < C1) {
        float m = g_sum1[tid] * invE;
        float v = g_ssq1[tid] * invE - m * m;
        float r = rsqrtf(v + 1e-5f);
        sr[tid] = r;
        sq[tid] = (b1[tid] - m) * r;
    }
    __syncthreads();
    const size_t total = (size_t)N * (C1 / 4);
    for (size_t i = (size_t)blockIdx.x * 256 + tid; i < total; i += (size_t)gridDim.x * 256) {
        int c = ((int)(i & 63)) * 4;
        float4 p = ((float4*)g_P)[i];
        float4 q = ((float4*)g_Q)[i];
        p.x *= sr[c + 0]; p.y *= sr[c + 1]; p.z *= sr[c + 2]; p.w *= sr[c + 3];
        q.x = q.x * sr[c + 0] + sq[c + 0];
        q.y = q.y * sr[c + 1] + sq[c + 1];
        q.z = q.z * sr[c + 2] + sq[c + 2];
        q.w = q.w * sr[c + 3] + sq[c + 3];
        ((float4*)g_P)[i] = p;
        ((float4*)g_Q)[i] = q;
    }
}

// ---------- K5: warp-specialized double-buffered relu(P'+Q') @ W2 -> g_h2 + stats2 ----
// 512 threads. Warps 0-7 consume (FFMA2 GEMM), warps 8-15 produce (stage xs).
// Chunk = 64 edges; two xs buffers [256][68]; ws [256][64].
#define XS_STRIDE (C1 * 68)                       // floats per xs buffer
#define SMEM2_FLOATS (C1 * C2 + 2 * XS_STRIDE)    // 16384 + 34816 = 51200
#define SMEM2_BYTES  (SMEM2_FLOATS * 4)           // 204800

__global__ void __launch_bounds__(512, 1) k_gemm2f(
    const float* __restrict__ W2, const float* __restrict__ b2, int E)
{
    extern __shared__ float smem[];
    float* ws = smem;                  // [256][64]
    float* xs = ws + C1 * C2;          // 2 x [256][68]

    __shared__ float bsum2[C2], bssq2[C2];

    const int tid = threadIdx.x;
    {
        const float4* w4 = (const float4*)W2;
        float4* ws4 = (float4*)ws;
        #pragma unroll 8
        for (int i = tid; i < C1 * C2 / 4; i += 512) ws4[i] = w4[i];
        if (tid < C2) { bsum2[tid] = 0.f; bssq2[tid] = 0.f; }
    }
    __syncthreads();

    const bool is_consumer = (tid < 256);
    const int nchunk = (E + 63) >> 6;

    float lsum[4], lssq[4];
    #pragma unroll
    for (int i = 0; i < 4; i++) { lsum[i] = 0.f; lssq[i] = 0.f; }

    int c0 = 0;
    if (is_consumer) {
        // consumer mapping: 16 channel groups x 4 ch ; 16 edge groups x 4 edges
        c0 = (tid & 15) * 4;
    }

    if (!is_consumer) {
        // ---------------- producer ----------------
        const int es = tid & 63;            // edge slot 0..63
        const int part = (tid >> 6) & 3;    // channel quarter
        const int c4base = part * 16;       // float4 channel base
        int it = 0;
        for (int ch = blockIdx.x; ch < nchunk; ch += gridDim.x, ++it) {
            const int buf = it & 1;
            if (it >= 2) BAR_SYNC(3 + buf);          // wait buffer free
            float* xw = xs + buf * XS_STRIDE;
            const int ge = (ch << 6) + es;
            if (ge < E) {
                int col = g_col[ge];
                int row = g_row[ge];
                const float4* pp = (const float4*)(g_P + (size_t)col * C1);
                const float4* qq = (const float4*)(g_Q + (size_t)row * C1);
                #pragma unroll 8
                for (int i = 0; i < 16; i++) {
                    int c4 = c4base + i;
                    float4 p = pp[c4], q = qq[c4];
                    int c = c4 * 4;
                    xw[(c + 0) * 68 + es] = fmaxf(p.x + q.x, 0.f);
                    xw[(c + 1) * 68 + es] = fmaxf(p.y + q.y, 0.f);
                    xw[(c + 2) * 68 + es] = fmaxf(p.z + q.z, 0.f);
                    xw[(c + 3) * 68 + es] = fmaxf(p.w + q.w, 0.f);
                }
            } else {
                #pragma unroll 8
                for (int i = 0; i < 16; i++) {
                    int c = (c4base + i) * 4;
                    xw[(c + 0) * 68 + es] = 0.f;
                    xw[(c + 1) * 68 + es] = 0.f;
                    xw[(c + 2) * 68 + es] = 0.f;
                    xw[(c + 3) * 68 + es] = 0.f;
                }
            }
            BAR_ARRIVE(1 + buf);                     // publish buffer full
        }
    } else {
        // ---------------- consumer ----------------
        const int eg = tid >> 4;            // 0..15 (4 edges each)
        const int xoff = eg * 4;
        float bb[4];
        #pragma unroll
        for (int i = 0; i < 4; i++) bb[i] = b2[c0 + i];

        int it = 0;
        for (int ch = blockIdx.x; ch < nchunk; ch += gridDim.x, ++it) {
            const int buf = it & 1;
            BAR_SYNC(1 + buf);                       // wait buffer full
            const float* xb = xs + buf * XS_STRIDE;

            unsigned long long acc[4][2];            // [channel][edge pair]
            #pragma unroll
            for (int c = 0; c < 4; c++) { acc[c][0] = 0ull; acc[c][1] = 0ull; }

            #pragma unroll 4
            for (int k = 0; k < C1; k++) {
                float4 w = *(const float4*)(ws + k * C2 + c0);
                unsigned long long wd0 = pack2(w.x, w.x);
                unsigned long long wd1 = pack2(w.y, w.y);
                unsigned long long wd2 = pack2(w.z, w.z);
                unsigned long long wd3 = pack2(w.w, w.w);
                ulonglong2 xa = *(const ulonglong2*)(xb + k * 68 + xoff);
                fma2(acc[0][0], wd0, xa.x); fma2(acc[0][1], wd0, xa.y);
                fma2(acc[1][0], wd1, xa.x); fma2(acc[1][1], wd1, xa.y);
                fma2(acc[2][0], wd2, xa.x); fma2(acc[2][1], wd2, xa.y);
                fma2(acc[3][0], wd3, xa.x); fma2(acc[3][1], wd3, xa.y);
            }
            BAR_ARRIVE(3 + buf);                     // release buffer

            float vv[4][4];                          // [channel][edge]
            #pragma unroll
            for (int c = 0; c < 4; c++) {
                float2 f0 = unpack2(acc[c][0]);
                float2 f1 = unpack2(acc[c][1]);
                vv[c][0] = f0.x + bb[c];
                vv[c][1] = f0.y + bb[c];
                vv[c][2] = f1.x + bb[c];
                vv[c][3] = f1.y + bb[c];
            }
            const int e0 = (ch << 6) + eg * 4;
            if ((ch << 6) + 64 <= E) {
                #pragma unroll
                for (int j = 0; j < 4; j++) {
                    float4 v = make_float4(vv[0][j], vv[1][j], vv[2][j], vv[3][j]);
                    *(float4*)&g_h2[(size_t)(e0 + j) * C2 + c0] = v;
                }
                #pragma unroll
                for (int c = 0; c < 4; c++)
                    #pragma unroll
                    for (int j = 0; j < 4; j++) {
                        lsum[c] += vv[c][j];
                        lssq[c] += vv[c][j] * vv[c][j];
                    }
            } else {
                for (int j = 0; j < 4; j++) {
                    int e = e0 + j;
                    if (e < E) {
                        #pragma unroll
                        for (int c = 0; c < 4; c++) {
                            g_h2[(size_t)e * C2 + c0 + c] = vv[c][j];
                            lsum[c] += vv[c][j];
                            lssq[c] += vv[c][j] * vv[c][j];
                        }
                    }
                }
            }
        }
    }

    if (is_consumer) {
        #pragma unroll
        for (int c = 0; c < 4; c++) {
            atomicAdd(&bsum2[c0 + c], lsum[c]);
            atomicAdd(&bssq2[c0 + c], lssq[c]);
        }
    }
    __syncthreads();
    if (tid < C2) {
        atomicAdd(&g_sum2[tid], bsum2[tid]);
        atomicAdd(&g_ssq2[tid], bssq2[tid]);
    }
}

// ---------- K6: norm+relu(h2) @ W3 + b3 -> out (finalize stats2 per-block) ----------
__global__ void __launch_bounds__(256) k_out(
    const float* __restrict__ W3, const float* __restrict__ b3,
    float* __restrict__ out, int E, float invE)
{
    __shared__ float w3s[C2], m2s[C2], r2s[C2];
    const int tid = threadIdx.x;
    if (tid < C2) {
        float m = g_sum2[tid] * invE;
        float v = g_ssq2[tid] * invE - m * m;
        m2s[tid] = m;
        r2s[tid] = rsqrtf(v + 1e-5f);
        w3s[tid] = W3[tid];
    }
    __syncthreads();
    const float b = b3[0];
    const int lane = tid & 31, wid = tid >> 5;
    const int q = lane & 3, el = lane >> 2;

    for (int base = blockIdx.x * 64; base < E; base += gridDim.x * 64) {
        int e = base + wid * 8 + el;
        float acc = 0.f;
        if (e < E) {
            const float4* rp = (const float4*)(g_h2 + (size_t)e * C2);
            #pragma unroll
            for (int t = 0; t < 4; t++) {
                float4 v = rp[q + 4 * t];
                int c = 16 * t + 4 * q;
                acc += fmaxf((v.x - m2s[c + 0]) * r2s[c + 0], 0.f) * w3s[c + 0];
                acc += fmaxf((v.y - m2s[c + 1]) * r2s[c + 1], 0.f) * w3s[c + 1];
                acc += fmaxf((v.z - m2s[c + 2]) * r2s[c + 2], 0.f) * w3s[c + 2];
                acc += fmaxf((v.w - m2s[c + 3]) * r2s[c + 3], 0.f) * w3s[c + 3];
            }
        }
        acc += __shfl_xor_sync(0xffffffffu, acc, 1);
        acc += __shfl_xor_sync(0xffffffffu, acc, 2);
        if (q == 0 && e < E) out[e] = acc + b;
    }
}

// ---------- launch ----------
extern "C" void kernel_launch(void* const* d_in, const int* in_sizes, int n_in,
                              void* d_out, int out_size) {
    const float* emb  = (const float*)d_in[0];
    const void*  eidx = d_in[1];
    const float* W1   = (const float*)d_in[2];
    const float* b1   = (const float*)d_in[3];
    const float* W2   = (const float*)d_in[4];
    const float* b2   = (const float*)d_in[5];
    const float* W3   = (const float*)d_in[6];
    const float* b3   = (const float*)d_in[7];
    float*       out  = (float*)d_out;

    const int N = in_sizes[0] / HDIM;
    const int E = in_sizes[1] / 2;
    if (E <= 0 || N <= 0 || N > NMAX || E > EMAXN) return;
    const float invE = 1.0f / (float)E;

    cudaFuncSetAttribute(k_pre,    cudaFuncAttributeMaxDynamicSharedMemorySize, SMEMP_BYTES);
    cudaFuncSetAttribute(k_gemm2f, cudaFuncAttributeMaxDynamicSharedMemorySize, SMEM2_BYTES);

    int cb = (E + 255) / 256; if (cb > 608) cb = 608;
    k_cvt_col<<<cb, 256>>>(eidx, E, N);
    k_cvt_row<<<cb, 256>>>(eidx, E, N);
    k_pre<<<152, 256, SMEMP_BYTES>>>(emb, W1, N);
    k_stats1<<<1216, 256>>>(b1, E);
    k_fold<<<608, 256>>>(b1, N, invE);
    k_gemm2f<<<152, 512, SMEM2_BYTES>>>(W2, b2, E);
    int nb = (E + 63) / 64;
    if (nb > 4864) nb = 4864;
    k_out<<<nb, 256>>>(W3, b3, out, E, invE);
}